// round 13
// baseline (speedup 1.0000x reference)
#include <cuda_runtime.h>
#include <cuda_fp16.h>
#include <math.h>
#include <float.h>
#include <stdint.h>

// ---------------- problem constants ----------------
#define N_POS 16384      // B*H*W
#define DIM   128
#define HW    1024
#define ZQ_ELEMS 2097152
#define LOSS_OFF 2097152
#define IDX_OFF  2097153
#define KCB   8192
#define N_ITERS 32       // 8192 / 256 codes per iteration
#define DELTA 0.025f     // admit margin (m units): worst-case fp16-accum + key quant

// ---------------- device scratch ----------------
__device__ float g_znorm[(size_t)N_POS * DIM];    // [n][c] for fp64 rescore
__device__ float g_znorm_t[(size_t)ZQ_ELEMS];     // [b][c][hw] for coalesced scatter
__device__ __align__(16) __half g_cs2h[KCB];      // half(2.0 + 0.5*||c||^2)
__device__ int   g_idx[N_POS];
__device__ float g_lossacc;
__device__ __align__(16) __half g_wh[(size_t)KCB * DIM];
__device__ __align__(16) __half g_zh[(size_t)N_POS * DIM];

// ---------------- smem layout (bytes) ----------------
#define PITCH_H 136              // halves per row (272B; 68%32==4 -> conflict-free)
#define ROW_B   272
#define A_B     34816            // 128 * 272
#define STAGE_B 69632            // 256 * 272
#define AH_B    0
#define BH_B    34816            // + buf*STAGE_B
#define CS_B    174080           // half [2][256] : 512 B per stage buffer
#define SM_TOTAL 175104

// ---------------- PTX helpers (sm_80-compatible only) ----------------
#define CP16(dst, src) \
    asm volatile("cp.async.cg.shared.global [%0], [%1], 16;" \
                 :: "r"(dst), "l"(src) : "memory")
#define CP_COMMIT() asm volatile("cp.async.commit_group;" ::: "memory")
#define CP_WAIT1()  asm volatile("cp.async.wait_group 1;" ::: "memory")
#define CP_WAIT0()  asm volatile("cp.async.wait_group 0;" ::: "memory")

#define LDMATRIX_X4(r0, r1, r2, r3, addr) \
    asm volatile("ldmatrix.sync.aligned.m8n8.x4.shared.b16 {%0,%1,%2,%3}, [%4];" \
                 : "=r"(r0), "=r"(r1), "=r"(r2), "=r"(r3) : "r"(addr))

__device__ __forceinline__ uint32_t smem_u32(const void* p) {
    uint32_t a;
    asm("{ .reg .u64 t; cvta.to.shared.u64 t, %1; cvt.u32.u64 %0, t; }" : "=r"(a) : "l"(p));
    return a;
}

// fp16-accumulator HMMA: D,C packed half2 x2 (potential 2x rate vs f32 accum)
__device__ __forceinline__ void mma16816_f16(uint32_t* c, const uint32_t* a, const uint32_t* b) {
    asm volatile(
        "mma.sync.aligned.m16n8k16.row.col.f16.f16.f16.f16 "
        "{%0,%1}, {%2,%3,%4,%5}, {%6,%7}, {%0,%1};"
        : "+r"(c[0]), "+r"(c[1])
        : "r"(a[0]), "r"(a[1]), "r"(a[2]), "r"(a[3]), "r"(b[0]), "r"(b[1]));
}

// ---------------------------------------------------------------------------
// Kernel A: L2 normalize; writes fp32 [n][c], fp32 transposed [b][c][hw],
// and fp16-hi rows for the HMMA screen.
// ---------------------------------------------------------------------------
__global__ void k_norm(const float* __restrict__ z) {
    int b   = blockIdx.x >> 3;
    int hw0 = (blockIdx.x & 7) << 7;
    int t   = threadIdx.x;

    const float* zb = z + (size_t)b * (DIM * HW);
    int col = hw0 + t;

    float s = 0.0f;
#pragma unroll 8
    for (int c = 0; c < DIM; c++) {
        float v = zb[c * HW + col];
        s = fmaf(v, v, s);
    }
    float den = fmaxf(sqrtf(s), 1e-12f);

    int n = b * HW + col;
    float* zn = g_znorm + (size_t)n * DIM;
    float* znt = g_znorm_t + (size_t)b * (DIM * HW);
    __half* zh = g_zh + (size_t)n * DIM;
#pragma unroll
    for (int c8 = 0; c8 < 16; c8++) {
        __align__(16) __half hb[8];
#pragma unroll
        for (int j = 0; j < 8; j++) {
            int c = c8 * 8 + j;
            float w = zb[c * HW + col] / den;
            zn[c] = w;
            znt[c * HW + col] = w;
            hb[j] = __float2half_rn(w);
        }
        *(uint4*)(zh + c8 * 8) = *(uint4*)hb;
    }
}

// ---------------------------------------------------------------------------
// Kernel B: code prep — half(2 + 0.5*||c||^2) and fp16-hi conversion.
// ---------------------------------------------------------------------------
__global__ void k_prep_w(const float* __restrict__ w) {
    int row = blockIdx.x;
    int t = threadIdx.x;
    float v = w[(size_t)row * DIM + t];
    g_wh[(size_t)row * DIM + t] = __float2half_rn(v);

    float sq = v * v;
    __shared__ float wsum[4];
#pragma unroll
    for (int off = 16; off; off >>= 1) sq += __shfl_down_sync(0xffffffffu, sq, off);
    if ((t & 31) == 0) wsum[t >> 5] = sq;
    __syncthreads();
    if (t == 0)
        g_cs2h[row] = __float2half_rn(2.0f + 0.5f * (wsum[0] + wsum[1] + wsum[2] + wsum[3]));
}

__global__ void k_reset() { g_lossacc = 0.0f; }

// ---------------------------------------------------------------------------
// 256-code stage cp.async issue (256 rows + cs2 halves), 256 threads
// ---------------------------------------------------------------------------
__device__ __forceinline__ void issue_b(uint32_t sb, int buf, int it, int tid) {
    const char* srcH = (const char*)(g_wh + (size_t)it * 256 * DIM);
    uint32_t dH = sb + BH_B + buf * STAGE_B;
#pragma unroll
    for (int r = 0; r < 16; r++) {
        int c = tid + 256 * r;          // 0..4095
        int row = c >> 4;
        int off = (c & 15) * 16;
        CP16(dH + row * ROW_B + off, srcH + row * 256 + off);
    }
    if (tid < 32)
        CP16(sb + CS_B + buf * 512 + tid * 16,
             (const char*)g_cs2h + (size_t)it * 512 + tid * 16);
}

// ---------------------------------------------------------------------------
// Main: fp16-accum HMMA screen + packed-key top-3 + fp64 rescore.
// 256 thr = 8 warps, warp grid 4(m) x 2(n), warp tile 32x64, 256 codes/iter.
// key = (halfbits(m) << 13) | code; m = half(2+0.5||c||^2) - dot > 0.
// ---------------------------------------------------------------------------
__global__ __launch_bounds__(256, 1)
void k_main_wmma(const float* __restrict__ weight, float* __restrict__ dout) {
    extern __shared__ __align__(16) unsigned char smem[];

    const int tid  = threadIdx.x;
    const int lane = tid & 31;
    const int wid  = tid >> 5;
    const int wm = wid & 3, wn = wid >> 2;
    const int gp = lane >> 2, qd = lane & 3;
    const int q0 = blockIdx.x << 7;

    uint32_t sb = smem_u32(smem);

    // ldmatrix per-lane addresses (b16 matrices)
    const uint32_t a_row = (uint32_t)(wm * 32 + (lane & 7) + ((lane >> 3) & 1) * 8);
    const uint32_t a_colb = (uint32_t)((lane >> 4) * 16);
    const uint32_t aoff0 = sb + AH_B + a_row * ROW_B + a_colb;   // + mi*16*ROW_B + ks*32
    const uint32_t b_row = (uint32_t)(wn * 64 + ((lane >> 4) ? 8 : 0) + (lane & 7));
    const uint32_t b_colb = (uint32_t)(((lane >> 3) & 1) * 16);
    const uint32_t boff0 = b_row * ROW_B + b_colb;               // + g*16*ROW_B + ks*32

    // prologue: A tile (once) + first two B stages
    {
        const char* srcH = (const char*)(g_zh + (size_t)q0 * DIM);
#pragma unroll
        for (int r = 0; r < 8; r++) {
            int c = tid + 256 * r;      // 0..2047
            int row = c >> 4;
            int off = (c & 15) * 16;
            CP16(sb + AH_B + row * ROW_B + off, srcH + row * 256 + off);
        }
        CP_COMMIT();
    }
    issue_b(sb, 0, 0, tid); CP_COMMIT();
    issue_b(sb, 1, 1, tid); CP_COMMIT();

    // packed top-3 keys per query-slot (4 slots/thread)
    int k1[4], k2[4], k3[4];
#pragma unroll
    for (int s = 0; s < 4; s++) { k1[s] = 0x7fffffff; k2[s] = 0x7fffffff; k3[s] = 0x7fffffff; }

    for (int i = 0; i < N_ITERS; i++) {
        int cur = i & 1;
        if (i < N_ITERS - 1) CP_WAIT1(); else CP_WAIT0();
        __syncthreads();

        uint32_t bstage = sb + BH_B + cur * STAGE_B;

#pragma unroll
        for (int hf = 0; hf < 2; hf++) {
            uint32_t bbase = bstage + (uint32_t)(hf * 128 * ROW_B) + boff0;

            uint32_t acc[2][8][2];     // packed half2 accumulators
#pragma unroll
            for (int mi = 0; mi < 2; mi++)
#pragma unroll
                for (int ni = 0; ni < 8; ni++) {
                    acc[mi][ni][0] = 0u; acc[mi][ni][1] = 0u;
                }

#pragma unroll
            for (int ks = 0; ks < 8; ks++) {
                uint32_t kb = (uint32_t)(ks * 32);
                uint32_t a[2][4], b[8][2];
#pragma unroll
                for (int mi = 0; mi < 2; mi++)
                    LDMATRIX_X4(a[mi][0], a[mi][1], a[mi][2], a[mi][3],
                                aoff0 + (uint32_t)(mi * 16 * ROW_B) + kb);
#pragma unroll
                for (int g = 0; g < 4; g++)
                    LDMATRIX_X4(b[2 * g][0], b[2 * g][1], b[2 * g + 1][0], b[2 * g + 1][1],
                                bbase + (uint32_t)(g * 16 * ROW_B) + kb);
#pragma unroll
                for (int mi = 0; mi < 2; mi++)
#pragma unroll
                    for (int ni = 0; ni < 8; ni++)
                        mma16816_f16(acc[mi][ni], a[mi], b[ni]);
            }

            // distance in half2 + packed-key top-3
            const __half2* cs = (const __half2*)(smem + CS_B + cur * 512 + hf * 256);
            int cbase = i * 256 + hf * 128 + wn * 64 + qd * 2;
#pragma unroll
            for (int ni = 0; ni < 8; ni++) {
                __half2 c2 = cs[(wn * 64 + ni * 8) / 2 + qd];    // cols qd*2, qd*2+1
                int c0 = cbase + ni * 8;
#pragma unroll
                for (int mi = 0; mi < 2; mi++)
#pragma unroll
                    for (int r = 0; r < 2; r++) {
                        __half2 m2 = __hsub2(c2, *(const __half2*)&acc[mi][ni][r]);
                        uint32_t u = *(const uint32_t*)&m2;
                        int s = mi * 2 + r;
                        int keyA = (int)(((u & 0xFFFFu) << 13) | (uint32_t)c0);
                        int keyB = (int)(((u >> 16) << 13) | (uint32_t)(c0 + 1));
#pragma unroll
                        for (int e = 0; e < 2; e++) {
                            int key = e ? keyB : keyA;
                            int lo = min(key, k1[s]);
                            int hi = max(key, k1[s]);
                            k1[s] = lo;
                            int lo2 = min(hi, k2[s]);
                            int hi2 = max(hi, k2[s]);
                            k2[s] = lo2;
                            k3[s] = min(k3[s], hi2);
                        }
                    }
            }
        }

        __syncthreads();
        if (i + 2 < N_ITERS) { issue_b(sb, cur, i + 2, tid); CP_COMMIT(); }
    }

    // cross-thread merge: per query row, 8 holder threads x 3 packed keys
    __syncthreads();
    uint4* red = (uint4*)smem;        // 128 * 8 * 16B = 16KB, overlays A tile
#pragma unroll
    for (int s = 0; s < 4; s++) {
        int row = wm * 32 + (s >> 1) * 16 + (s & 1) * 8 + gp;
        red[row * 8 + wn * 4 + qd] = make_uint4((uint32_t)k1[s], (uint32_t)k2[s],
                                                (uint32_t)k3[s], 0u);
    }
    __syncthreads();

    if (tid < 128) {
        int n = q0 + tid;
        int mink = 0x7fffffff;
#pragma unroll
        for (int e = 0; e < 8; e++) {
            uint4 t = red[tid * 8 + e];
            mink = min(mink, (int)t.x);
        }
        unsigned short mb0 = (unsigned short)(((uint32_t)mink >> 13) & 0xFFFFu);
        float cut = __half2float(*(const __half*)&mb0) + DELTA;
        int ck[24]; int cnt = 0;
#pragma unroll
        for (int e = 0; e < 8; e++) {
            uint4 t = red[tid * 8 + e];
            uint32_t ks3[3] = { t.x, t.y, t.z };
#pragma unroll
            for (int j = 0; j < 3; j++) {
                unsigned short hb = (unsigned short)((ks3[j] >> 13) & 0xFFFFu);
                if ((int)ks3[j] != 0x7fffffff &&
                    __half2float(*(const __half*)&hb) <= cut)
                    ck[cnt++] = (int)(ks3[j] & 0x1FFFu);
            }
        }
        int best;
        if (cnt == 1) {
            best = ck[0];           // unique within margin -> argmin
        } else {
            // fp64 exact rescoring of all admitted candidates
            const float* zr = g_znorm + (size_t)n * DIM;
            double bq = 1e300; best = 0x7fffffff;
            for (int e = 0; e < cnt; e++) {
                int k = ck[e];
                const float* wr = weight + (size_t)k * DIM;
                double dot = 0.0, csq = 0.0;
                for (int d = 0; d < DIM; d++) {
                    double wv = wr[d];
                    dot += (double)zr[d] * wv;
                    csq += wv * wv;
                }
                double q = csq - 2.0 * dot;
                if (q < bq || (q == bq && k < best)) { bq = q; best = k; }
            }
        }
        g_idx[n] = best;
        dout[IDX_OFF + n] = (float)best;
    }
}

// ---------------------------------------------------------------------------
// gather z_q, straight-through output, loss partials (znorm_t: coalesced)
// ---------------------------------------------------------------------------
__global__ void k_scatter(const float* __restrict__ weight, float* __restrict__ dout) {
    int o = blockIdx.x * 256 + threadIdx.x;
    int b  = o >> 17;
    int c  = (o >> 10) & 127;
    int hw = o & 1023;
    int n  = (b << 10) | hw;
    int idx = g_idx[n] & (KCB - 1);   // defensive clamp

    float wv = weight[(size_t)idx * DIM + c];
    float zt = g_znorm_t[o];
    float diff = __fsub_rn(wv, zt);
    dout[o] = __fadd_rn(zt, diff);

    float sq = diff * diff;
    __shared__ float wsum[8];
#pragma unroll
    for (int off = 16; off; off >>= 1) sq += __shfl_down_sync(0xffffffffu, sq, off);
    if ((threadIdx.x & 31) == 0) wsum[threadIdx.x >> 5] = sq;
    __syncthreads();
    if (threadIdx.x < 8) {
        float v = wsum[threadIdx.x];
#pragma unroll
        for (int off = 4; off; off >>= 1) v += __shfl_down_sync(0xffu, v, off);
        if (threadIdx.x == 0) atomicAdd(&g_lossacc, v);
    }
}

__global__ void k_loss(float* __restrict__ dout) {
    dout[LOSS_OFF] = 0.25f * g_lossacc / (float)ZQ_ELEMS;
}

// ---------------------------------------------------------------------------
extern "C" void kernel_launch(void* const* d_in, const int* in_sizes, int n_in,
                              void* d_out, int out_size) {
    const float* z = (const float*)d_in[0];
    const float* w = (const float*)d_in[1];
    float* out = (float*)d_out;

    cudaFuncSetAttribute(k_main_wmma, cudaFuncAttributeMaxDynamicSharedMemorySize, SM_TOTAL);

    k_norm<<<128, 128>>>(z);               // launch 0
    k_prep_w<<<KCB, 128>>>(w);             // launch 1
    k_reset<<<1, 1>>>();                   // launch 2 (positions k_main at ncu slot 3)
    k_main_wmma<<<N_POS / 128, 256, SM_TOTAL>>>(w, out);   // launch 3 <- profiled
    k_scatter<<<ZQ_ELEMS / 256, 256>>>(w, out);
    k_loss<<<1, 1>>>(out);
}

// round 14
// speedup vs baseline: 1.4407x; 1.4407x over previous
#include <cuda_runtime.h>
#include <cuda_fp16.h>
#include <math.h>
#include <float.h>
#include <stdint.h>

// ---------------- problem constants ----------------
#define N_POS 16384      // B*H*W
#define DIM   128
#define HW    1024
#define ZQ_ELEMS 2097152
#define LOSS_OFF 2097152
#define IDX_OFF  2097153
#define KCB   8192
#define N_UNITS 8192     // 128 tiles * 64 chunks
#define N_CTAS 148       // persistent grid: one CTA per SM
#define CAND_STRIDE 48   // max candidate keys per query (<=3 segments * 16)
#define DELTA 5.0e-3f    // admit margin: 2*fp16 dot err + 2*key quantization

// ---------------- device scratch ----------------
__device__ float g_znorm[(size_t)N_POS * DIM];    // [n][c] for fp64 rescore
__device__ float g_znorm_t[(size_t)ZQ_ELEMS];     // [b][c][hw] for coalesced scatter
__device__ __align__(16) float g_cs2[KCB];        // 2.0 + 0.5*||c||^2
__device__ int   g_idx[N_POS];
__device__ float g_lossacc;
__device__ int   g_ccnt[N_POS];
__device__ int   g_cand[(size_t)N_POS * CAND_STRIDE];
__device__ __align__(16) __half g_wh[(size_t)KCB * DIM];
__device__ __align__(16) __half g_zh[(size_t)N_POS * DIM];

// ---------------- smem layout (bytes) ----------------
#define ROW_B   272              // 136 halves per row (68 words %32==4 -> conflict-free)
#define TILE_B  34816            // 128 * 272
#define AH_B    0
#define BH_B    34816            // + buf*TILE_B
#define CS_B    104448           // float [2][128]
#define SBASE_B 105472           // int [128] flush slot bases
#define SM_TOTAL 105984

// ---------------- PTX helpers (sm_80-compatible only) ----------------
#define CP16(dst, src) \
    asm volatile("cp.async.cg.shared.global [%0], [%1], 16;" \
                 :: "r"(dst), "l"(src) : "memory")
#define CP_COMMIT() asm volatile("cp.async.commit_group;" ::: "memory")
#define CP_WAIT1()  asm volatile("cp.async.wait_group 1;" ::: "memory")
#define CP_WAIT0()  asm volatile("cp.async.wait_group 0;" ::: "memory")

#define LDMATRIX_X4(r0, r1, r2, r3, addr) \
    asm volatile("ldmatrix.sync.aligned.m8n8.x4.shared.b16 {%0,%1,%2,%3}, [%4];" \
                 : "=r"(r0), "=r"(r1), "=r"(r2), "=r"(r3) : "r"(addr))

__device__ __forceinline__ uint32_t smem_u32(const void* p) {
    uint32_t a;
    asm("{ .reg .u64 t; cvta.to.shared.u64 t, %1; cvt.u32.u64 %0, t; }" : "=r"(a) : "l"(p));
    return a;
}

__device__ __forceinline__ void mma16816(float* c, const uint32_t* a, const uint32_t* b) {
    asm volatile(
        "mma.sync.aligned.m16n8k16.row.col.f32.f16.f16.f32 "
        "{%0,%1,%2,%3}, {%4,%5,%6,%7}, {%8,%9}, {%0,%1,%2,%3};"
        : "+f"(c[0]), "+f"(c[1]), "+f"(c[2]), "+f"(c[3])
        : "r"(a[0]), "r"(a[1]), "r"(a[2]), "r"(a[3]), "r"(b[0]), "r"(b[1]));
}

// ---------------------------------------------------------------------------
// Kernel A: L2 normalize; fp32 [n][c], fp32 transposed [b][c][hw], fp16-hi.
// ---------------------------------------------------------------------------
__global__ void k_norm(const float* __restrict__ z) {
    int b   = blockIdx.x >> 3;
    int hw0 = (blockIdx.x & 7) << 7;
    int t   = threadIdx.x;

    const float* zb = z + (size_t)b * (DIM * HW);
    int col = hw0 + t;

    float s = 0.0f;
#pragma unroll 8
    for (int c = 0; c < DIM; c++) {
        float v = zb[c * HW + col];
        s = fmaf(v, v, s);
    }
    float den = fmaxf(sqrtf(s), 1e-12f);

    int n = b * HW + col;
    float* zn = g_znorm + (size_t)n * DIM;
    float* znt = g_znorm_t + (size_t)b * (DIM * HW);
    __half* zh = g_zh + (size_t)n * DIM;
#pragma unroll
    for (int c8 = 0; c8 < 16; c8++) {
        __align__(16) __half hb[8];
#pragma unroll
        for (int j = 0; j < 8; j++) {
            int c = c8 * 8 + j;
            float w = zb[c * HW + col] / den;
            zn[c] = w;
            znt[c * HW + col] = w;
            hb[j] = __float2half_rn(w);
        }
        *(uint4*)(zh + c8 * 8) = *(uint4*)hb;
    }
}

// ---------------------------------------------------------------------------
// Kernel B: code prep — 2 + 0.5*||c||^2 and fp16-hi conversion.
// ---------------------------------------------------------------------------
__global__ void k_prep_w(const float* __restrict__ w) {
    int row = blockIdx.x;
    int t = threadIdx.x;
    float v = w[(size_t)row * DIM + t];
    g_wh[(size_t)row * DIM + t] = __float2half_rn(v);

    float sq = v * v;
    __shared__ float wsum[4];
#pragma unroll
    for (int off = 16; off; off >>= 1) sq += __shfl_down_sync(0xffffffffu, sq, off);
    if ((t & 31) == 0) wsum[t >> 5] = sq;
    __syncthreads();
    if (t == 0)
        g_cs2[row] = 2.0f + 0.5f * (wsum[0] + wsum[1] + wsum[2] + wsum[3]);
}

__global__ void k_reset() {
    int n = blockIdx.x * 256 + threadIdx.x;
    g_ccnt[n] = 0;
    if (n == 0) g_lossacc = 0.0f;
}

// ---------------------------------------------------------------------------
// 128-code chunk cp.async issue (Bh tile + cs2 floats), 256 threads
// ---------------------------------------------------------------------------
__device__ __forceinline__ void issue_b(uint32_t sb, int buf, int chunk, int tid) {
    const char* srcH = (const char*)(g_wh + (size_t)chunk * 128 * DIM);
    uint32_t dH = sb + BH_B + buf * TILE_B;
#pragma unroll
    for (int r = 0; r < 8; r++) {
        int c = tid + 256 * r;          // 0..2047
        int row = c >> 4;
        int off = (c & 15) * 16;
        CP16(dH + row * ROW_B + off, srcH + row * 256 + off);
    }
    if (tid < 32)
        CP16(sb + CS_B + buf * 512 + tid * 16,
             (const char*)g_cs2 + (size_t)chunk * 512 + tid * 16);
}

// ---------------------------------------------------------------------------
// Main: persistent K-split. 148 CTAs x 256 threads; CTA g owns contiguous
// work units [g*8192/148, (g+1)*8192/148), unit = tile*64 + chunk.
// Per segment: load A tile, run f32-accum HMMA screen with packed-key top-2,
// flush ALL 16 holder keys per query to the global candidate buffer.
// ---------------------------------------------------------------------------
__global__ __launch_bounds__(256, 1)
void k_main_split(float* __restrict__ dout) {
    extern __shared__ __align__(16) unsigned char smem[];

    const int tid  = threadIdx.x;
    const int lane = tid & 31;
    const int wid  = tid >> 5;
    const int wm = wid & 3, wn = wid >> 2;
    const int gp = lane >> 2, qd = lane & 3;
    const int g = blockIdx.x;

    uint32_t sb = smem_u32(smem);
    int* sbase = (int*)(smem + SBASE_B);

    // ldmatrix per-lane addresses
    const uint32_t a_row = (uint32_t)(wm * 32 + (lane & 7) + ((lane >> 3) & 1) * 8);
    const uint32_t a_colb = (uint32_t)((lane >> 4) * 16);
    const uint32_t aoff0 = sb + AH_B + a_row * ROW_B + a_colb;
    const uint32_t b_row = (uint32_t)(wn * 64 + ((lane >> 4) ? 8 : 0) + (lane & 7));
    const uint32_t b_colb = (uint32_t)(((lane >> 3) & 1) * 16);
    const uint32_t boff0 = b_row * ROW_B + b_colb;

    int u  = (int)((long long)g * N_UNITS / N_CTAS);
    int u1 = (int)((long long)(g + 1) * N_UNITS / N_CTAS);

    while (u < u1) {
        int tile = u >> 6;
        int cs = u & 63;
        int ce = min(64, cs + (u1 - u));
        int q0 = tile << 7;

        // segment prologue: A tile + first two B chunks
        {
            const char* srcH = (const char*)(g_zh + (size_t)q0 * DIM);
#pragma unroll
            for (int r = 0; r < 8; r++) {
                int c = tid + 256 * r;
                int row = c >> 4;
                int off = (c & 15) * 16;
                CP16(sb + AH_B + row * ROW_B + off, srcH + row * 256 + off);
            }
            CP_COMMIT();
        }
        issue_b(sb, 0, cs, tid); CP_COMMIT();
        if (cs + 1 < ce) issue_b(sb, 1, cs + 1, tid);
        CP_COMMIT();

        int k1[4], k2[4];
#pragma unroll
        for (int s = 0; s < 4; s++) { k1[s] = 0x7fffffff; k2[s] = 0x7fffffff; }

        for (int c = cs; c < ce; c++) {
            int cur = (c - cs) & 1;
            if (c < ce - 1) CP_WAIT1(); else CP_WAIT0();
            __syncthreads();

            uint32_t bbase = sb + BH_B + cur * TILE_B + boff0;

            float acc[2][8][4];
#pragma unroll
            for (int mi = 0; mi < 2; mi++)
#pragma unroll
                for (int ni = 0; ni < 8; ni++)
#pragma unroll
                    for (int v = 0; v < 4; v++) acc[mi][ni][v] = 0.0f;

#pragma unroll
            for (int ks = 0; ks < 8; ks++) {
                uint32_t kb = (uint32_t)(ks * 32);
                uint32_t a[2][4], b[8][2];
#pragma unroll
                for (int mi = 0; mi < 2; mi++)
                    LDMATRIX_X4(a[mi][0], a[mi][1], a[mi][2], a[mi][3],
                                aoff0 + (uint32_t)(mi * 16 * ROW_B) + kb);
#pragma unroll
                for (int gq = 0; gq < 4; gq++)
                    LDMATRIX_X4(b[2 * gq][0], b[2 * gq][1], b[2 * gq + 1][0], b[2 * gq + 1][1],
                                bbase + (uint32_t)(gq * 16 * ROW_B) + kb);
#pragma unroll
                for (int mi = 0; mi < 2; mi++)
#pragma unroll
                    for (int ni = 0; ni < 8; ni++)
                        mma16816(acc[mi][ni], a[mi], b[ni]);
            }

            // fused distance + packed-key top-2
            const float* csf = (const float*)(smem + CS_B + cur * 512);
            int cbase = c * 128 + wn * 64 + qd * 2;
#pragma unroll
            for (int ni = 0; ni < 8; ni++) {
                float2 c2 = *(const float2*)(csf + wn * 64 + ni * 8 + qd * 2);
                int c0 = cbase + ni * 8;
                int c1 = c0 + 1;
#pragma unroll
                for (int mi = 0; mi < 2; mi++)
#pragma unroll
                    for (int v = 0; v < 4; v++) {
                        float m = ((v & 1) ? c2.y : c2.x) - acc[mi][ni][v];
                        int key = (int)((__float_as_uint(m) & 0xFFFFE000u) |
                                        (uint32_t)((v & 1) ? c1 : c0));
                        int s = mi * 2 + (v >> 1);
                        int lo = min(key, k1[s]);
                        int hi = max(key, k1[s]);
                        k1[s] = lo;
                        k2[s] = min(k2[s], hi);
                    }
            }

            __syncthreads();
            if (c + 2 < ce) { issue_b(sb, cur, c + 2, tid); CP_COMMIT(); }
        }

        // segment flush: all 16 holder keys per query -> global candidates
        if (tid < 128) {
            int base = atomicAdd(&g_ccnt[q0 + tid], 16);
            sbase[tid] = min(base, CAND_STRIDE - 16);
        }
        __syncthreads();
#pragma unroll
        for (int s = 0; s < 4; s++) {
            int row = wm * 32 + (s >> 1) * 16 + (s & 1) * 8 + gp;
            int* dst = g_cand + (size_t)(q0 + row) * CAND_STRIDE + sbase[row] + (wn * 4 + qd) * 2;
            dst[0] = k1[s];
            dst[1] = k2[s];
        }
        __syncthreads();

        u += ce - cs;
    }
}

// ---------------------------------------------------------------------------
// Merge: per query, global min over candidates, admit within DELTA, fp64
// rescore when ambiguous. 16384 threads.
// ---------------------------------------------------------------------------
__global__ void k_merge(const float* __restrict__ weight, float* __restrict__ dout) {
    int n = blockIdx.x * 256 + threadIdx.x;
    int cnt = min(g_ccnt[n], CAND_STRIDE);
    const int* cand = g_cand + (size_t)n * CAND_STRIDE;

    int mink = 0x7fffffff;
    for (int e = 0; e < cnt; e++) mink = min(mink, cand[e]);

    float cut = __uint_as_float((uint32_t)mink & 0xFFFFE000u) + DELTA;
    int ck[CAND_STRIDE]; int cc = 0;
    for (int e = 0; e < cnt; e++) {
        int key = cand[e];
        if (key != 0x7fffffff &&
            __uint_as_float((uint32_t)key & 0xFFFFE000u) <= cut)
            ck[cc++] = key & 0x1FFF;
    }

    int best;
    if (cc == 1) {
        best = ck[0];
    } else {
        const float* zr = g_znorm + (size_t)n * DIM;
        double bq = 1e300; best = 0x7fffffff;
        for (int e = 0; e < cc; e++) {
            int k = ck[e];
            const float* wr = weight + (size_t)k * DIM;
            double dot = 0.0, csq = 0.0;
            for (int d = 0; d < DIM; d++) {
                double wv = wr[d];
                dot += (double)zr[d] * wv;
                csq += wv * wv;
            }
            double q = csq - 2.0 * dot;
            if (q < bq || (q == bq && k < best)) { bq = q; best = k; }
        }
    }
    g_idx[n] = best;
    dout[IDX_OFF + n] = (float)best;
}

// ---------------------------------------------------------------------------
// gather z_q, straight-through output, loss partials (znorm_t: coalesced)
// ---------------------------------------------------------------------------
__global__ void k_scatter(const float* __restrict__ weight, float* __restrict__ dout) {
    int o = blockIdx.x * 256 + threadIdx.x;
    int b  = o >> 17;
    int c  = (o >> 10) & 127;
    int hw = o & 1023;
    int n  = (b << 10) | hw;
    int idx = g_idx[n] & (KCB - 1);   // defensive clamp

    float wv = weight[(size_t)idx * DIM + c];
    float zt = g_znorm_t[o];
    float diff = __fsub_rn(wv, zt);
    dout[o] = __fadd_rn(zt, diff);

    float sq = diff * diff;
    __shared__ float wsum[8];
#pragma unroll
    for (int off = 16; off; off >>= 1) sq += __shfl_down_sync(0xffffffffu, sq, off);
    if ((threadIdx.x & 31) == 0) wsum[threadIdx.x >> 5] = sq;
    __syncthreads();
    if (threadIdx.x < 8) {
        float v = wsum[threadIdx.x];
#pragma unroll
        for (int off = 4; off; off >>= 1) v += __shfl_down_sync(0xffu, v, off);
        if (threadIdx.x == 0) atomicAdd(&g_lossacc, v);
    }
}

__global__ void k_loss(float* __restrict__ dout) {
    dout[LOSS_OFF] = 0.25f * g_lossacc / (float)ZQ_ELEMS;
}

// ---------------------------------------------------------------------------
extern "C" void kernel_launch(void* const* d_in, const int* in_sizes, int n_in,
                              void* d_out, int out_size) {
    const float* z = (const float*)d_in[0];
    const float* w = (const float*)d_in[1];
    float* out = (float*)d_out;

    cudaFuncSetAttribute(k_main_split, cudaFuncAttributeMaxDynamicSharedMemorySize, SM_TOTAL);

    k_norm<<<128, 128>>>(z);               // launch 0
    k_prep_w<<<KCB, 128>>>(w);             // launch 1
    k_reset<<<N_POS / 256, 256>>>();       // launch 2
    k_main_split<<<N_CTAS, 256, SM_TOTAL>>>(out);          // launch 3 <- profiled
    k_merge<<<N_POS / 256, 256>>>(w, out); // launch 4
    k_scatter<<<ZQ_ELEMS / 256, 256>>>(w, out);
    k_loss<<<1, 1>>>(out);
}

// round 15
// speedup vs baseline: 2.5506x; 1.7703x over previous
#include <cuda_runtime.h>
#include <cuda_fp16.h>
#include <math.h>
#include <float.h>
#include <stdint.h>

// ---------------- problem constants ----------------
#define N_POS 16384      // B*H*W
#define DIM   128
#define HW    1024
#define ZQ_ELEMS 2097152
#define LOSS_OFF 2097152
#define IDX_OFF  2097153
#define KCB   8192
#define N_UNITS 8192     // 128 tiles * 64 chunks
#define N_CTAS 148       // persistent grid: one CTA per SM
#define CAND_STRIDE 48   // max candidate keys per query (<=3 segments * 16)
#define DELTA 5.0e-3f    // admit margin: 2*fp16 dot err + 2*key quantization

// ---------------- device scratch ----------------
__device__ float g_znorm[(size_t)N_POS * DIM];    // [n][c] for exact rescore
__device__ float g_znorm_t[(size_t)ZQ_ELEMS];     // [b][c][hw] for coalesced scatter
__device__ __align__(16) float g_cs2[KCB];        // 2.0 + 0.5*||c||^2
__device__ int   g_idx[N_POS];
__device__ float g_lossacc;
__device__ int   g_ccnt[N_POS];
__device__ int   g_cand[(size_t)N_POS * CAND_STRIDE];
__device__ __align__(16) __half g_wh[(size_t)KCB * DIM];
__device__ __align__(16) __half g_zh[(size_t)N_POS * DIM];

// ---------------- smem layout (bytes) ----------------
#define ROW_B   272              // 136 halves per row (68 words %32==4 -> conflict-free)
#define TILE_B  34816            // 128 * 272
#define AH_B    0
#define BH_B    34816            // + buf*TILE_B
#define CS_B    104448           // float [2][128]
#define SBASE_B 105472           // int [128] flush slot bases
#define SM_TOTAL 105984

// ---------------- PTX helpers (sm_80-compatible only) ----------------
#define CP16(dst, src) \
    asm volatile("cp.async.cg.shared.global [%0], [%1], 16;" \
                 :: "r"(dst), "l"(src) : "memory")
#define CP_COMMIT() asm volatile("cp.async.commit_group;" ::: "memory")
#define CP_WAIT1()  asm volatile("cp.async.wait_group 1;" ::: "memory")
#define CP_WAIT0()  asm volatile("cp.async.wait_group 0;" ::: "memory")

#define LDMATRIX_X4(r0, r1, r2, r3, addr) \
    asm volatile("ldmatrix.sync.aligned.m8n8.x4.shared.b16 {%0,%1,%2,%3}, [%4];" \
                 : "=r"(r0), "=r"(r1), "=r"(r2), "=r"(r3) : "r"(addr))

__device__ __forceinline__ uint32_t smem_u32(const void* p) {
    uint32_t a;
    asm("{ .reg .u64 t; cvta.to.shared.u64 t, %1; cvt.u32.u64 %0, t; }" : "=r"(a) : "l"(p));
    return a;
}

__device__ __forceinline__ void mma16816(float* c, const uint32_t* a, const uint32_t* b) {
    asm volatile(
        "mma.sync.aligned.m16n8k16.row.col.f32.f16.f16.f32 "
        "{%0,%1,%2,%3}, {%4,%5,%6,%7}, {%8,%9}, {%0,%1,%2,%3};"
        : "+f"(c[0]), "+f"(c[1]), "+f"(c[2]), "+f"(c[3])
        : "r"(a[0]), "r"(a[1]), "r"(a[2]), "r"(a[3]), "r"(b[0]), "r"(b[1]));
}

// TwoSum accumulate: (s, c) += x, error-free
__device__ __forceinline__ void ds_add(float& s, float& c, float x) {
    float t = s + x;
    float bb = t - s;
    float err = (s - (t - bb)) + (x - bb);
    s = t;
    c += err;
}

// ---------------------------------------------------------------------------
// Kernel A: L2 normalize; fp32 [n][c], fp32 transposed [b][c][hw], fp16-hi.
// ---------------------------------------------------------------------------
__global__ void k_norm(const float* __restrict__ z) {
    int b   = blockIdx.x >> 3;
    int hw0 = (blockIdx.x & 7) << 7;
    int t   = threadIdx.x;

    const float* zb = z + (size_t)b * (DIM * HW);
    int col = hw0 + t;

    float s = 0.0f;
#pragma unroll 8
    for (int c = 0; c < DIM; c++) {
        float v = zb[c * HW + col];
        s = fmaf(v, v, s);
    }
    float den = fmaxf(sqrtf(s), 1e-12f);

    int n = b * HW + col;
    float* zn = g_znorm + (size_t)n * DIM;
    float* znt = g_znorm_t + (size_t)b * (DIM * HW);
    __half* zh = g_zh + (size_t)n * DIM;
#pragma unroll
    for (int c8 = 0; c8 < 16; c8++) {
        __align__(16) __half hb[8];
#pragma unroll
        for (int j = 0; j < 8; j++) {
            int c = c8 * 8 + j;
            float w = zb[c * HW + col] / den;
            zn[c] = w;
            znt[c * HW + col] = w;
            hb[j] = __float2half_rn(w);
        }
        *(uint4*)(zh + c8 * 8) = *(uint4*)hb;
    }
}

// ---------------------------------------------------------------------------
// Kernel B: code prep — 2 + 0.5*||c||^2 and fp16-hi conversion.
// ---------------------------------------------------------------------------
__global__ void k_prep_w(const float* __restrict__ w) {
    int row = blockIdx.x;
    int t = threadIdx.x;
    float v = w[(size_t)row * DIM + t];
    g_wh[(size_t)row * DIM + t] = __float2half_rn(v);

    float sq = v * v;
    __shared__ float wsum[4];
#pragma unroll
    for (int off = 16; off; off >>= 1) sq += __shfl_down_sync(0xffffffffu, sq, off);
    if ((t & 31) == 0) wsum[t >> 5] = sq;
    __syncthreads();
    if (t == 0)
        g_cs2[row] = 2.0f + 0.5f * (wsum[0] + wsum[1] + wsum[2] + wsum[3]);
}

__global__ void k_reset() {
    int n = blockIdx.x * 256 + threadIdx.x;
    g_ccnt[n] = 0;
    if (n == 0) g_lossacc = 0.0f;
}

// ---------------------------------------------------------------------------
// 128-code chunk cp.async issue (Bh tile + cs2 floats), 256 threads
// ---------------------------------------------------------------------------
__device__ __forceinline__ void issue_b(uint32_t sb, int buf, int chunk, int tid) {
    const char* srcH = (const char*)(g_wh + (size_t)chunk * 128 * DIM);
    uint32_t dH = sb + BH_B + buf * TILE_B;
#pragma unroll
    for (int r = 0; r < 8; r++) {
        int c = tid + 256 * r;          // 0..2047
        int row = c >> 4;
        int off = (c & 15) * 16;
        CP16(dH + row * ROW_B + off, srcH + row * 256 + off);
    }
    if (tid < 32)
        CP16(sb + CS_B + buf * 512 + tid * 16,
             (const char*)g_cs2 + (size_t)chunk * 512 + tid * 16);
}

// ---------------------------------------------------------------------------
// Main: persistent K-split. 148 CTAs x 256 threads; CTA g owns contiguous
// work units [g*8192/148, (g+1)*8192/148), unit = tile*64 + chunk.
// f32-accum HMMA screen + packed-key top-2; flush 16 holder keys/query.
// ---------------------------------------------------------------------------
__global__ __launch_bounds__(256, 1)
void k_main_split(float* __restrict__ dout) {
    extern __shared__ __align__(16) unsigned char smem[];

    const int tid  = threadIdx.x;
    const int lane = tid & 31;
    const int wid  = tid >> 5;
    const int wm = wid & 3, wn = wid >> 2;
    const int gp = lane >> 2, qd = lane & 3;
    const int g = blockIdx.x;

    uint32_t sb = smem_u32(smem);
    int* sbase = (int*)(smem + SBASE_B);

    const uint32_t a_row = (uint32_t)(wm * 32 + (lane & 7) + ((lane >> 3) & 1) * 8);
    const uint32_t a_colb = (uint32_t)((lane >> 4) * 16);
    const uint32_t aoff0 = sb + AH_B + a_row * ROW_B + a_colb;
    const uint32_t b_row = (uint32_t)(wn * 64 + ((lane >> 4) ? 8 : 0) + (lane & 7));
    const uint32_t b_colb = (uint32_t)(((lane >> 3) & 1) * 16);
    const uint32_t boff0 = b_row * ROW_B + b_colb;

    int u  = (int)((long long)g * N_UNITS / N_CTAS);
    int u1 = (int)((long long)(g + 1) * N_UNITS / N_CTAS);

    while (u < u1) {
        int tile = u >> 6;
        int cs = u & 63;
        int ce = min(64, cs + (u1 - u));
        int q0 = tile << 7;

        {
            const char* srcH = (const char*)(g_zh + (size_t)q0 * DIM);
#pragma unroll
            for (int r = 0; r < 8; r++) {
                int c = tid + 256 * r;
                int row = c >> 4;
                int off = (c & 15) * 16;
                CP16(sb + AH_B + row * ROW_B + off, srcH + row * 256 + off);
            }
            CP_COMMIT();
        }
        issue_b(sb, 0, cs, tid); CP_COMMIT();
        if (cs + 1 < ce) issue_b(sb, 1, cs + 1, tid);
        CP_COMMIT();

        int k1[4], k2[4];
#pragma unroll
        for (int s = 0; s < 4; s++) { k1[s] = 0x7fffffff; k2[s] = 0x7fffffff; }

        for (int c = cs; c < ce; c++) {
            int cur = (c - cs) & 1;
            if (c < ce - 1) CP_WAIT1(); else CP_WAIT0();
            __syncthreads();

            uint32_t bbase = sb + BH_B + cur * TILE_B + boff0;

            float acc[2][8][4];
#pragma unroll
            for (int mi = 0; mi < 2; mi++)
#pragma unroll
                for (int ni = 0; ni < 8; ni++)
#pragma unroll
                    for (int v = 0; v < 4; v++) acc[mi][ni][v] = 0.0f;

#pragma unroll
            for (int ks = 0; ks < 8; ks++) {
                uint32_t kb = (uint32_t)(ks * 32);
                uint32_t a[2][4], b[8][2];
#pragma unroll
                for (int mi = 0; mi < 2; mi++)
                    LDMATRIX_X4(a[mi][0], a[mi][1], a[mi][2], a[mi][3],
                                aoff0 + (uint32_t)(mi * 16 * ROW_B) + kb);
#pragma unroll
                for (int gq = 0; gq < 4; gq++)
                    LDMATRIX_X4(b[2 * gq][0], b[2 * gq][1], b[2 * gq + 1][0], b[2 * gq + 1][1],
                                bbase + (uint32_t)(gq * 16 * ROW_B) + kb);
#pragma unroll
                for (int mi = 0; mi < 2; mi++)
#pragma unroll
                    for (int ni = 0; ni < 8; ni++)
                        mma16816(acc[mi][ni], a[mi], b[ni]);
            }

            const float* csf = (const float*)(smem + CS_B + cur * 512);
            int cbase = c * 128 + wn * 64 + qd * 2;
#pragma unroll
            for (int ni = 0; ni < 8; ni++) {
                float2 c2 = *(const float2*)(csf + wn * 64 + ni * 8 + qd * 2);
                int c0 = cbase + ni * 8;
                int c1 = c0 + 1;
#pragma unroll
                for (int mi = 0; mi < 2; mi++)
#pragma unroll
                    for (int v = 0; v < 4; v++) {
                        float m = ((v & 1) ? c2.y : c2.x) - acc[mi][ni][v];
                        int key = (int)((__float_as_uint(m) & 0xFFFFE000u) |
                                        (uint32_t)((v & 1) ? c1 : c0));
                        int s = mi * 2 + (v >> 1);
                        int lo = min(key, k1[s]);
                        int hi = max(key, k1[s]);
                        k1[s] = lo;
                        k2[s] = min(k2[s], hi);
                    }
            }

            __syncthreads();
            if (c + 2 < ce) { issue_b(sb, cur, c + 2, tid); CP_COMMIT(); }
        }

        if (tid < 128) {
            int base = atomicAdd(&g_ccnt[q0 + tid], 16);
            sbase[tid] = min(base, CAND_STRIDE - 16);
        }
        __syncthreads();
#pragma unroll
        for (int s = 0; s < 4; s++) {
            int row = wm * 32 + (s >> 1) * 16 + (s & 1) * 8 + gp;
            int* dst = g_cand + (size_t)(q0 + row) * CAND_STRIDE + sbase[row] + (wn * 4 + qd) * 2;
            dst[0] = k1[s];
            dst[1] = k2[s];
        }
        __syncthreads();

        u += ce - cs;
    }
}

// ---------------------------------------------------------------------------
// Merge: per query, global min over candidates, admit within DELTA, exact
// rescore in DOUBLE-SINGLE (compensated fp32 — no slow FP64 in the hot path).
// ---------------------------------------------------------------------------
__global__ void k_merge(const float* __restrict__ weight, float* __restrict__ dout) {
    int n = blockIdx.x * 128 + threadIdx.x;
    int cnt = min(g_ccnt[n], CAND_STRIDE);
    const int* cand = g_cand + (size_t)n * CAND_STRIDE;

    int mink = 0x7fffffff;
    for (int e = 0; e < cnt; e++) mink = min(mink, cand[e]);

    float cut = __uint_as_float((uint32_t)mink & 0xFFFFE000u) + DELTA;
    int ck[CAND_STRIDE]; int cc = 0;
    for (int e = 0; e < cnt; e++) {
        int key = cand[e];
        if (key != 0x7fffffff &&
            __uint_as_float((uint32_t)key & 0xFFFFE000u) <= cut)
            ck[cc++] = key & 0x1FFF;
    }

    int best;
    if (cc == 1) {
        best = ck[0];
    } else {
        const float4* zr = (const float4*)(g_znorm + (size_t)n * DIM);
        double bq = 1e300; best = 0x7fffffff;
        for (int e = 0; e < cc; e++) {
            int k = ck[e];
            const float4* wr = (const float4*)(weight + (size_t)k * DIM);
            float s = 0.0f, comp = 0.0f;
#pragma unroll 4
            for (int d4 = 0; d4 < DIM / 4; d4++) {
                float4 wv = wr[d4];
                float4 zv = zr[d4];
                float wa[4] = { wv.x, wv.y, wv.z, wv.w };
                float za[4] = { zv.x, zv.y, zv.z, zv.w };
#pragma unroll
                for (int j = 0; j < 4; j++) {
                    float w = wa[j];
                    float zn2 = -2.0f * za[j];          // exact (scale by 2)
                    float p1 = w * w;
                    float e1 = fmaf(w, w, -p1);         // TwoProd error
                    float p2 = zn2 * w;
                    float e2 = fmaf(zn2, w, -p2);       // TwoProd error
                    ds_add(s, comp, p1);
                    ds_add(s, comp, p2);
                    ds_add(s, comp, e1);
                    ds_add(s, comp, e2);
                }
            }
            double q = (double)s + (double)comp;        // one cheap fp64 add
            if (q < bq || (q == bq && k < best)) { bq = q; best = k; }
        }
    }
    g_idx[n] = best;
    dout[IDX_OFF + n] = (float)best;
}

// ---------------------------------------------------------------------------
// gather z_q, straight-through output, loss partials (znorm_t: coalesced)
// ---------------------------------------------------------------------------
__global__ void k_scatter(const float* __restrict__ weight, float* __restrict__ dout) {
    int o = blockIdx.x * 256 + threadIdx.x;
    int b  = o >> 17;
    int c  = (o >> 10) & 127;
    int hw = o & 1023;
    int n  = (b << 10) | hw;
    int idx = g_idx[n] & (KCB - 1);   // defensive clamp

    float wv = weight[(size_t)idx * DIM + c];
    float zt = g_znorm_t[o];
    float diff = __fsub_rn(wv, zt);
    dout[o] = __fadd_rn(zt, diff);

    float sq = diff * diff;
    __shared__ float wsum[8];
#pragma unroll
    for (int off = 16; off; off >>= 1) sq += __shfl_down_sync(0xffffffffu, sq, off);
    if ((threadIdx.x & 31) == 0) wsum[threadIdx.x >> 5] = sq;
    __syncthreads();
    if (threadIdx.x < 8) {
        float v = wsum[threadIdx.x];
#pragma unroll
        for (int off = 4; off; off >>= 1) v += __shfl_down_sync(0xffu, v, off);
        if (threadIdx.x == 0) atomicAdd(&g_lossacc, v);
    }
}

__global__ void k_loss(float* __restrict__ dout) {
    dout[LOSS_OFF] = 0.25f * g_lossacc / (float)ZQ_ELEMS;
}

// ---------------------------------------------------------------------------
extern "C" void kernel_launch(void* const* d_in, const int* in_sizes, int n_in,
                              void* d_out, int out_size) {
    const float* z = (const float*)d_in[0];
    const float* w = (const float*)d_in[1];
    float* out = (float*)d_out;

    cudaFuncSetAttribute(k_main_split, cudaFuncAttributeMaxDynamicSharedMemorySize, SM_TOTAL);

    k_norm<<<128, 128>>>(z);               // launch 0
    k_prep_w<<<KCB, 128>>>(w);             // launch 1
    k_reset<<<N_POS / 256, 256>>>();       // launch 2
    k_main_split<<<N_CTAS, 256, SM_TOTAL>>>(out);          // launch 3
    k_merge<<<N_POS / 128, 128>>>(w, out); // launch 4
    k_scatter<<<ZQ_ELEMS / 256, 256>>>(w, out);
    k_loss<<<1, 1>>>(out);
}